// round 16
// baseline (speedup 1.0000x reference)
#include <cuda_runtime.h>
#include <cuda_fp16.h>
#include <cuda_bf16.h>
#include <cstdint>

// Problem dims
#define B_ 1024
#define C_ 65536
#define D_ 512
#define NT64 (C_ / 64)                            // 1024 64-wide tiles per row

// ---------------- scratch (device globals; no runtime allocation) ----------------
__device__ __half   g_xh[(size_t)B_ * D_];        // 1 MB fp16 x
__device__ __half   g_kh[(size_t)C_ * D_];        // 64 MB fp16 keys
__device__ uint8_t  g_ws8[(size_t)B_ * C_];       // 64 MB quantized ws (u8)
__device__ uint8_t  g_tmax8[(size_t)B_ * NT64];   // 1 MB per-(row,64tile) max (u8)
__device__ float    g_off[B_];                    // per-row u8 quantization offset
__device__ unsigned g_rowmax[B_];                 // order-encoded fp32 row max
#define CAP 512
__device__ int      g_n[B_];                      // per-row final candidate count
__device__ int      g_widx[(size_t)B_ * CAP];     // per-row candidate indices (sorted)
__device__ float    g_w[(size_t)B_ * CAP];        // per-row normalized weights

#define QS 3.5f                                   // u8 units per ws unit
#define MARGIN 12.0f                              // softmax-tail truncation margin

#define SW128(o)   ((o) ^ (((o) >> 3) & 0x70))

__device__ __forceinline__ uint32_t smem_u32(const void* p) {
    uint32_t a;
    asm("{ .reg .u64 t; cvta.to.shared.u64 t, %1; cvt.u32.u64 %0, t; }" : "=r"(a) : "l"(p));
    return a;
}

__device__ __forceinline__ void ldsm4(uint32_t& r0, uint32_t& r1, uint32_t& r2, uint32_t& r3, uint32_t a) {
    asm volatile("ldmatrix.sync.aligned.m8n8.x4.shared.b16 {%0,%1,%2,%3}, [%4];"
                 : "=r"(r0), "=r"(r1), "=r"(r2), "=r"(r3) : "r"(a));
}

// fp16 inputs, fp16 accumulators
__device__ __forceinline__ void mma16816h(uint32_t* c, const uint32_t* a, uint32_t b0, uint32_t b1) {
    asm volatile(
        "mma.sync.aligned.m16n8k16.row.col.f16.f16.f16.f16 "
        "{%0,%1}, {%2,%3,%4,%5}, {%6,%7}, {%0,%1};"
        : "+r"(c[0]), "+r"(c[1])
        : "r"(a[0]), "r"(a[1]), "r"(a[2]), "r"(a[3]), "r"(b0), "r"(b1));
}

// order-preserving float<->uint encoding for atomicMax
__device__ __forceinline__ unsigned fenc(float f) {
    unsigned u = __float_as_uint(f);
    return (u & 0x80000000u) ? ~u : (u | 0x80000000u);
}
__device__ __forceinline__ float fdec(unsigned u) {
    return (u & 0x80000000u) ? __uint_as_float(u & 0x7fffffffu) : __uint_as_float(~u);
}

// ---------------- kernel 1: keys fp32 -> fp16 (MLP-4 per thread) ---------------
#define CONV_STRIDE 2097152                       // float4s per batch
__global__ void __launch_bounds__(256) conv_kernel(const float* __restrict__ keys) {
    size_t i = (size_t)blockIdx.x * 256 + threadIdx.x;   // 0 .. 2097151
    float4 v[4];
    #pragma unroll
    for (int j = 0; j < 4; j++) v[j] = ((const float4*)keys)[i + (size_t)j * CONV_STRIDE];
    #pragma unroll
    for (int j = 0; j < 4; j++) {
        __half2 a = __floats2half2_rn(v[j].x, v[j].y);
        __half2 b = __floats2half2_rn(v[j].z, v[j].w);
        uint2 o; o.x = *(const unsigned*)&a; o.y = *(const unsigned*)&b;
        ((uint2*)g_kh)[i + (size_t)j * CONV_STRIDE] = o;
    }
}

// ---------------- kernel 1b: x fp32->fp16 + ||x|| offset + rowmax init ---------
__global__ void __launch_bounds__(256) xnorm_kernel(const float* __restrict__ x,
                                                    const float* __restrict__ logt) {
    int row = blockIdx.x * 8 + (threadIdx.x >> 5);
    int lane = threadIdx.x & 31;
    if (row >= B_) return;
    const float4* r4 = (const float4*)(x + (size_t)row * D_);
    float4 v[4];
    float ss = 0.f;
    #pragma unroll
    for (int j = 0; j < 4; j++) {
        v[j] = r4[lane + 32 * j];
        ss += v[j].x * v[j].x + v[j].y * v[j].y + v[j].z * v[j].z + v[j].w * v[j].w;
    }
    #pragma unroll
    for (int j = 0; j < 4; j++) {
        __half2 a = __floats2half2_rn(v[j].x, v[j].y);
        __half2 b = __floats2half2_rn(v[j].z, v[j].w);
        uint2 o; o.x = *(const unsigned*)&a; o.y = *(const unsigned*)&b;
        ((uint2*)(g_xh + (size_t)row * D_))[lane + 32 * j] = o;
    }
    #pragma unroll
    for (int o = 16; o; o >>= 1) ss += __shfl_xor_sync(0xffffffffu, ss, o);
    if (lane == 0) {
        float inv_t = __expf(-logt[0]);
        g_off[row] = 4.2f * sqrtf(ss) * inv_t - 45.f;
        g_rowmax[row] = 0u;
    }
}

// ---------------- kernel 2: fp16 HMMA GEMM (fp16 accum, u8 + tmax epilogue) ----
#define KC 64
#define CHUNK_BYTES 16384
#define BUF_BYTES   32768
#define SMEM_ALLOC  (2 * BUF_BYTES + 1024)

__device__ __forceinline__ void ldg_chunk(uint4* st, const __half* Ag,
                                          const __half* Bg, int k0, int tid) {
    #pragma unroll
    for (int j = 0; j < 4; j++) {
        int u = j * 256 + tid;
        st[j] = *(const uint4*)(Ag + (size_t)(u >> 3) * D_ + k0 + (u & 7) * 8);
    }
    #pragma unroll
    for (int j = 0; j < 4; j++) {
        int u = j * 256 + tid;
        st[4 + j] = *(const uint4*)(Bg + (size_t)(u >> 3) * D_ + k0 + (u & 7) * 8);
    }
}

__device__ __forceinline__ void sts_chunk(char* buf, const uint4* st, int tid) {
    #pragma unroll
    for (int j = 0; j < 4; j++) {
        int u = j * 256 + tid;
        uint32_t off = SW128((uint32_t)((u >> 3) * 128 + (u & 7) * 16));
        *(uint4*)(buf + off) = st[j];
    }
    #pragma unroll
    for (int j = 0; j < 4; j++) {
        int u = j * 256 + tid;
        uint32_t off = SW128((uint32_t)((u >> 3) * 128 + (u & 7) * 16));
        *(uint4*)(buf + CHUNK_BYTES + off) = st[4 + j];
    }
}

__global__ void __launch_bounds__(256, 2) gemm_kernel(const float* __restrict__ logt) {
    extern __shared__ char smraw[];
    uint32_t sbr = smem_u32(smraw);
    uint32_t sb = (sbr + 1023u) & ~1023u;
    char* smem = smraw + (sb - sbr);

    int tid = threadIdx.x;
    int wid = tid >> 5, lane = tid & 31;
    int wm = wid >> 1, wn = wid & 1;
    int mt = blockIdx.x & 7;           // consecutive blocks share keys tile (L2)
    int nt = blockIdx.x >> 3;
    int q0 = mt * 128, c0 = nt * 128;

    const __half* Ag = g_xh + (size_t)q0 * D_;
    const __half* Bg = g_kh + (size_t)c0 * D_;

    uint32_t acc[2][8][2];
    #pragma unroll
    for (int t = 0; t < 2; t++)
        #pragma unroll
        for (int n = 0; n < 8; n++) { acc[t][n][0] = 0u; acc[t][n][1] = 0u; }

    uint4 st[8];
    ldg_chunk(st, Ag, Bg, 0, tid);
    sts_chunk(smem, st, tid);
    __syncthreads();

    int aRow = wm * 32 + ((lane >> 3) & 1) * 8 + (lane & 7);
    uint32_t aColB = (uint32_t)((lane >> 4) * 16);
    int bm = lane >> 3;
    int bRowIn = (bm >> 1) * 8 + (lane & 7);
    uint32_t bColB = (uint32_t)((bm & 1) * 16);

    #pragma unroll 1
    for (int i = 0; i < 8; i++) {
        if (i < 7) ldg_chunk(st, Ag, Bg, (i + 1) * KC, tid);

        uint32_t bufA = sb + (i & 1) * BUF_BYTES;
        uint32_t bufB = bufA + CHUNK_BYTES;
        #pragma unroll
        for (int ks = 0; ks < 4; ks++) {
            uint32_t kb = (uint32_t)(ks * 32);
            uint32_t a[2][4];
            #pragma unroll
            for (int t = 0; t < 2; t++) {
                uint32_t off = (uint32_t)((aRow + t * 16) * 128) + kb + aColB;
                ldsm4(a[t][0], a[t][1], a[t][2], a[t][3], bufA + SW128(off));
            }
            #pragma unroll
            for (int p = 0; p < 4; p++) {
                uint32_t b0, b1, b2, b3;
                uint32_t off = (uint32_t)((wn * 64 + p * 16 + bRowIn) * 128) + kb + bColB;
                ldsm4(b0, b1, b2, b3, bufB + SW128(off));
                #pragma unroll
                for (int t = 0; t < 2; t++) {
                    mma16816h(acc[t][p * 2 + 0], a[t], b0, b1);
                    mma16816h(acc[t][p * 2 + 1], a[t], b2, b3);
                }
            }
        }
        __syncthreads();
        if (i < 7) {
            sts_chunk(smem + ((i + 1) & 1) * BUF_BYTES, st, tid);
            __syncthreads();
        }
    }

    // epilogue: u8 quantized store + u8 tile-max + fp32 rowmax atomics
    float inv_t = __expf(-logt[0]);
    int g = lane >> 2, tig = lane & 3;
    #pragma unroll
    for (int t = 0; t < 2; t++) {
        #pragma unroll
        for (int h = 0; h < 2; h++) {
            int q = q0 + wm * 32 + t * 16 + h * 8 + g;
            float off = g_off[q];
            uint8_t* dst = g_ws8 + (size_t)q * C_ + c0 + wn * 64;
            float lmax = -3.4e38f;
            #pragma unroll
            for (int n = 0; n < 8; n++) {
                __half2 hv = *(__half2*)&acc[t][n][h];
                float v0 = __low2float(hv) * inv_t;
                float v1 = __high2float(hv) * inv_t;
                lmax = fmaxf(lmax, fmaxf(v0, v1));
                int u0 = __float2int_rn(fminf(fmaxf((v0 - off) * QS, 0.f), 255.f));
                int u1 = __float2int_rn(fminf(fmaxf((v1 - off) * QS, 0.f), 255.f));
                *(unsigned short*)(dst + n * 8 + tig * 2) =
                    (unsigned short)(u0 | (u1 << 8));
            }
            lmax = fmaxf(lmax, __shfl_xor_sync(0xffffffffu, lmax, 1));
            lmax = fmaxf(lmax, __shfl_xor_sync(0xffffffffu, lmax, 2));
            if (tig == 0) {
                int ut = __float2int_rn(fminf(fmaxf((lmax - off) * QS, 0.f), 255.f));
                g_tmax8[(size_t)q * NT64 + nt * 2 + wn] = (uint8_t)ut;
                atomicMax(&g_rowmax[q], fenc(lmax));
            }
        }
    }
}

// ---------------- kernel 3a: select + exact rescore + softmax -> weight lists --
__global__ void __launch_bounds__(256) sel_kernel(
    const float* __restrict__ x, const float* __restrict__ keys,
    const float* __restrict__ logt)
{
    __shared__ float xs[D_];
    __shared__ int   tlist[NT64];
    __shared__ int   craw[CAP];
    __shared__ int   cidx[CAP];
    __shared__ float cw[CAP];
    __shared__ float red[256];
    __shared__ int   tcnt, cnt;

    int q = blockIdx.x;
    int tid = threadIdx.x;
    float inv_t = __expf(-logt[0]);

    xs[tid] = x[(size_t)q * D_ + tid];
    xs[tid + 256] = x[(size_t)q * D_ + tid + 256];
    if (tid == 0) { tcnt = 0; cnt = 0; }
    __syncthreads();

    float mx = fdec(g_rowmax[q]);
    float thr = mx - (MARGIN + 0.001f * fabsf(mx) + 0.8f * inv_t);
    float off = g_off[q];
    int thr_u = (int)floorf((thr - off) * QS);
    thr_u = min(max(thr_u, 0), 254);
    uint32_t thrb = (uint32_t)thr_u * 0x01010101u;

    // phase 1: tile-max scan (1 KB)
    uint32_t tw = ((const uint32_t*)(g_tmax8 + (size_t)q * NT64))[tid];
    uint32_t tmsk = __vcmpgtu4(tw, thrb);
    while (tmsk) {
        int b = (__ffs(tmsk) - 1) >> 3;
        tmsk &= ~(0xFFu << (b * 8));
        int p = atomicAdd(&tcnt, 1);
        tlist[p] = tid * 4 + b;
    }
    __syncthreads();
    int ntl = min(tcnt, NT64);

    // phase 2: candidate extraction, half-warp per tile
    int hw = tid >> 4, l16 = tid & 15;
    const uint8_t* wrow = g_ws8 + (size_t)q * C_;
    for (int t = hw; t < ntl; t += 16) {
        int tile = tlist[t];
        uint32_t v = __ldg((const uint32_t*)(wrow + tile * 64) + l16);
        uint32_t m = __vcmpgtu4(v, thrb);
        while (m) {
            int b = (__ffs(m) - 1) >> 3;
            m &= ~(0xFFu << (b * 8));
            int p = atomicAdd(&cnt, 1);
            if (p < CAP) craw[p] = tile * 64 + l16 * 4 + b;
        }
    }
    __syncthreads();
    int n = min(cnt, CAP);

    // parallel rank sort (indices distinct); deterministic order
    for (int i = tid; i < n; i += 256) {
        int key = craw[i];
        int rank = 0;
        for (int j = 0; j < n; j++) rank += (craw[j] < key);
        cidx[rank] = key;
    }
    __syncthreads();

    // exact fp32 ws for selected candidates (one warp per candidate, 8 warps)
    int w = tid >> 5, lane = tid & 31;
    for (int i = w; i < n; i += 8) {
        const float* kr = keys + (size_t)cidx[i] * D_;
        float s = 0.f;
        #pragma unroll
        for (int kk = 0; kk < 16; kk++) s += xs[lane + kk * 32] * __ldg(kr + lane + kk * 32);
        #pragma unroll
        for (int o = 16; o; o >>= 1) s += __shfl_xor_sync(0xffffffffu, s, o);
        if (lane == 0) cw[i] = s * inv_t;
    }
    __syncthreads();

    // exact max over selected
    float lm = -3.4e38f;
    for (int i = tid; i < n; i += 256) lm = fmaxf(lm, cw[i]);
    red[tid] = lm; __syncthreads();
    for (int s2 = 128; s2; s2 >>= 1) { if (tid < s2) red[tid] = fmaxf(red[tid], red[tid + s2]); __syncthreads(); }
    float m = red[0]; __syncthreads();

    // exp + sum
    float ls = 0.f;
    for (int i = tid; i < n; i += 256) { float e = __expf(cw[i] - m); cw[i] = e; ls += e; }
    red[tid] = ls; __syncthreads();
    for (int s2 = 128; s2; s2 >>= 1) { if (tid < s2) red[tid] += red[tid + s2]; __syncthreads(); }
    float invS = 1.0f / red[0]; __syncthreads();

    // write compact normalized weight list
    for (int i = tid; i < n; i += 256) {
        g_widx[(size_t)q * CAP + i] = cidx[i];
        g_w[(size_t)q * CAP + i] = cw[i] * invS;
    }
    if (tid == 0) g_n[q] = n;
}

// ---------------- kernel 3b: weighted gather (2 blocks per row) ----------------
__global__ void __launch_bounds__(256) gather_kernel(
    const float* __restrict__ values, float* __restrict__ out)
{
    __shared__ int   sidx[CAP];
    __shared__ float sw[CAP];

    int q = blockIdx.x >> 1;
    int half = blockIdx.x & 1;
    int tid = threadIdx.x;
    int n = g_n[q];

    for (int i = tid; i < n; i += 256) {
        sidx[i] = g_widx[(size_t)q * CAP + i];
        sw[i]   = g_w[(size_t)q * CAP + i];
    }
    __syncthreads();

    int d = half * 256 + tid;
    float a0 = 0.f;
    #pragma unroll 8
    for (int i = 0; i < n; i++) {
        a0 += sw[i] * __ldg(values + (size_t)sidx[i] * D_ + d);
    }
    out[(size_t)q * D_ + d] = a0;
}

// ---------------- launch ----------------
extern "C" void kernel_launch(void* const* d_in, const int* in_sizes, int n_in,
                              void* d_out, int out_size) {
    const float* x      = (const float*)d_in[0];
    const float* keys   = (const float*)d_in[1];
    const float* values = (const float*)d_in[2];
    const float* logt   = (const float*)d_in[3];
    float* out = (float*)d_out;

    static bool attr_done = false;
    if (!attr_done) {
        cudaFuncSetAttribute(gemm_kernel, cudaFuncAttributeMaxDynamicSharedMemorySize, SMEM_ALLOC);
        attr_done = true;
    }

    conv_kernel<<<CONV_STRIDE / 256, 256>>>(keys);
    xnorm_kernel<<<B_ / 8, 256>>>(x, logt);
    gemm_kernel<<<(B_ / 128) * (C_ / 128), 256, SMEM_ALLOC>>>(logt);
    sel_kernel<<<B_, 256>>>(x, keys, logt);
    gather_kernel<<<B_ * 2, 256>>>(values, out);
}

// round 17
// speedup vs baseline: 1.4641x; 1.4641x over previous
#include <cuda_runtime.h>
#include <cuda_fp16.h>
#include <cuda_bf16.h>
#include <cstdint>

// Problem dims
#define B_ 1024
#define C_ 65536
#define D_ 512
#define NT64 (C_ / 64)                            // 1024 64-wide tiles per row

// ---------------- scratch (device globals; no runtime allocation) ----------------
__device__ __half   g_xh[(size_t)B_ * D_];        // 1 MB fp16 x
__device__ __half   g_kh[(size_t)C_ * D_];        // 64 MB fp16 keys
__device__ uint8_t  g_ws8[(size_t)B_ * C_];       // 64 MB quantized ws (u8)
__device__ uint8_t  g_tmax8[(size_t)B_ * NT64];   // 1 MB per-(row,64tile) max (u8)
__device__ float    g_off[B_];                    // per-row u8 quantization offset
__device__ unsigned g_rowmax[B_];                 // order-encoded fp32 row max
#define CAP 512
__device__ int      g_n[B_];                      // per-row final candidate count
__device__ int      g_widx[(size_t)B_ * CAP];     // per-row candidate indices (sorted)
__device__ float    g_w[(size_t)B_ * CAP];        // per-row normalized weights

#define QS 3.5f                                   // u8 units per ws unit
#define MARGIN 12.0f                              // softmax-tail truncation margin

#define SW128(o)   ((o) ^ (((o) >> 3) & 0x70))

__device__ __forceinline__ uint32_t smem_u32(const void* p) {
    uint32_t a;
    asm("{ .reg .u64 t; cvta.to.shared.u64 t, %1; cvt.u32.u64 %0, t; }" : "=r"(a) : "l"(p));
    return a;
}

__device__ __forceinline__ void ldsm4(uint32_t& r0, uint32_t& r1, uint32_t& r2, uint32_t& r3, uint32_t a) {
    asm volatile("ldmatrix.sync.aligned.m8n8.x4.shared.b16 {%0,%1,%2,%3}, [%4];"
                 : "=r"(r0), "=r"(r1), "=r"(r2), "=r"(r3) : "r"(a));
}

// fp16 inputs, fp16 accumulators
__device__ __forceinline__ void mma16816h(uint32_t* c, const uint32_t* a, uint32_t b0, uint32_t b1) {
    asm volatile(
        "mma.sync.aligned.m16n8k16.row.col.f16.f16.f16.f16 "
        "{%0,%1}, {%2,%3,%4,%5}, {%6,%7}, {%0,%1};"
        : "+r"(c[0]), "+r"(c[1])
        : "r"(a[0]), "r"(a[1]), "r"(a[2]), "r"(a[3]), "r"(b0), "r"(b1));
}

// order-preserving float<->uint encoding for atomicMax
__device__ __forceinline__ unsigned fenc(float f) {
    unsigned u = __float_as_uint(f);
    return (u & 0x80000000u) ? ~u : (u | 0x80000000u);
}
__device__ __forceinline__ float fdec(unsigned u) {
    return (u & 0x80000000u) ? __uint_as_float(u & 0x7fffffffu) : __uint_as_float(~u);
}

// ---------------- kernel 1: keys fp32 -> fp16 (MLP-4 per thread) ---------------
#define CONV_STRIDE 2097152                       // float4s per batch
__global__ void __launch_bounds__(256) conv_kernel(const float* __restrict__ keys) {
    size_t i = (size_t)blockIdx.x * 256 + threadIdx.x;   // 0 .. 2097151
    float4 v[4];
    #pragma unroll
    for (int j = 0; j < 4; j++) v[j] = ((const float4*)keys)[i + (size_t)j * CONV_STRIDE];
    #pragma unroll
    for (int j = 0; j < 4; j++) {
        __half2 a = __floats2half2_rn(v[j].x, v[j].y);
        __half2 b = __floats2half2_rn(v[j].z, v[j].w);
        uint2 o; o.x = *(const unsigned*)&a; o.y = *(const unsigned*)&b;
        ((uint2*)g_kh)[i + (size_t)j * CONV_STRIDE] = o;
    }
}

// ---------------- kernel 1b: x fp32->fp16 + ||x|| offset + rowmax init ---------
__global__ void __launch_bounds__(256) xnorm_kernel(const float* __restrict__ x,
                                                    const float* __restrict__ logt) {
    int row = blockIdx.x * 8 + (threadIdx.x >> 5);
    int lane = threadIdx.x & 31;
    if (row >= B_) return;
    const float4* r4 = (const float4*)(x + (size_t)row * D_);
    float4 v[4];
    float ss = 0.f;
    #pragma unroll
    for (int j = 0; j < 4; j++) {
        v[j] = r4[lane + 32 * j];
        ss += v[j].x * v[j].x + v[j].y * v[j].y + v[j].z * v[j].z + v[j].w * v[j].w;
    }
    #pragma unroll
    for (int j = 0; j < 4; j++) {
        __half2 a = __floats2half2_rn(v[j].x, v[j].y);
        __half2 b = __floats2half2_rn(v[j].z, v[j].w);
        uint2 o; o.x = *(const unsigned*)&a; o.y = *(const unsigned*)&b;
        ((uint2*)(g_xh + (size_t)row * D_))[lane + 32 * j] = o;
    }
    #pragma unroll
    for (int o = 16; o; o >>= 1) ss += __shfl_xor_sync(0xffffffffu, ss, o);
    if (lane == 0) {
        float inv_t = __expf(-logt[0]);
        g_off[row] = 4.2f * sqrtf(ss) * inv_t - 45.f;
        g_rowmax[row] = 0u;
    }
}

// ---------------- kernel 2: fp16 HMMA GEMM (fp16 accum, u8 + tmax epilogue) ----
#define KC 64
#define CHUNK_BYTES 16384
#define BUF_BYTES   32768
#define SMEM_ALLOC  (2 * BUF_BYTES + 1024)

__device__ __forceinline__ void ldg_chunk(uint4* st, const __half* Ag,
                                          const __half* Bg, int k0, int tid) {
    #pragma unroll
    for (int j = 0; j < 4; j++) {
        int u = j * 256 + tid;
        st[j] = *(const uint4*)(Ag + (size_t)(u >> 3) * D_ + k0 + (u & 7) * 8);
    }
    #pragma unroll
    for (int j = 0; j < 4; j++) {
        int u = j * 256 + tid;
        st[4 + j] = *(const uint4*)(Bg + (size_t)(u >> 3) * D_ + k0 + (u & 7) * 8);
    }
}

__device__ __forceinline__ void sts_chunk(char* buf, const uint4* st, int tid) {
    #pragma unroll
    for (int j = 0; j < 4; j++) {
        int u = j * 256 + tid;
        uint32_t off = SW128((uint32_t)((u >> 3) * 128 + (u & 7) * 16));
        *(uint4*)(buf + off) = st[j];
    }
    #pragma unroll
    for (int j = 0; j < 4; j++) {
        int u = j * 256 + tid;
        uint32_t off = SW128((uint32_t)((u >> 3) * 128 + (u & 7) * 16));
        *(uint4*)(buf + CHUNK_BYTES + off) = st[4 + j];
    }
}

__global__ void __launch_bounds__(256, 2) gemm_kernel(const float* __restrict__ logt) {
    extern __shared__ char smraw[];
    uint32_t sbr = smem_u32(smraw);
    uint32_t sb = (sbr + 1023u) & ~1023u;
    char* smem = smraw + (sb - sbr);

    int tid = threadIdx.x;
    int wid = tid >> 5, lane = tid & 31;
    int wm = wid >> 1, wn = wid & 1;
    int mt = blockIdx.x & 7;           // consecutive blocks share keys tile (L2)
    int nt = blockIdx.x >> 3;
    int q0 = mt * 128, c0 = nt * 128;

    const __half* Ag = g_xh + (size_t)q0 * D_;
    const __half* Bg = g_kh + (size_t)c0 * D_;

    uint32_t acc[2][8][2];
    #pragma unroll
    for (int t = 0; t < 2; t++)
        #pragma unroll
        for (int n = 0; n < 8; n++) { acc[t][n][0] = 0u; acc[t][n][1] = 0u; }

    uint4 st[8];
    ldg_chunk(st, Ag, Bg, 0, tid);
    sts_chunk(smem, st, tid);
    __syncthreads();

    int aRow = wm * 32 + ((lane >> 3) & 1) * 8 + (lane & 7);
    uint32_t aColB = (uint32_t)((lane >> 4) * 16);
    int bm = lane >> 3;
    int bRowIn = (bm >> 1) * 8 + (lane & 7);
    uint32_t bColB = (uint32_t)((bm & 1) * 16);

    #pragma unroll 1
    for (int i = 0; i < 8; i++) {
        if (i < 7) ldg_chunk(st, Ag, Bg, (i + 1) * KC, tid);

        uint32_t bufA = sb + (i & 1) * BUF_BYTES;
        uint32_t bufB = bufA + CHUNK_BYTES;
        #pragma unroll
        for (int ks = 0; ks < 4; ks++) {
            uint32_t kb = (uint32_t)(ks * 32);
            uint32_t a[2][4];
            #pragma unroll
            for (int t = 0; t < 2; t++) {
                uint32_t off = (uint32_t)((aRow + t * 16) * 128) + kb + aColB;
                ldsm4(a[t][0], a[t][1], a[t][2], a[t][3], bufA + SW128(off));
            }
            #pragma unroll
            for (int p = 0; p < 4; p++) {
                uint32_t b0, b1, b2, b3;
                uint32_t off = (uint32_t)((wn * 64 + p * 16 + bRowIn) * 128) + kb + bColB;
                ldsm4(b0, b1, b2, b3, bufB + SW128(off));
                #pragma unroll
                for (int t = 0; t < 2; t++) {
                    mma16816h(acc[t][p * 2 + 0], a[t], b0, b1);
                    mma16816h(acc[t][p * 2 + 1], a[t], b2, b3);
                }
            }
        }
        __syncthreads();
        if (i < 7) {
            sts_chunk(smem + ((i + 1) & 1) * BUF_BYTES, st, tid);
            __syncthreads();
        }
    }

    // epilogue: u8 quantized store + u8 tile-max + fp32 rowmax atomics
    float inv_t = __expf(-logt[0]);
    int g = lane >> 2, tig = lane & 3;
    #pragma unroll
    for (int t = 0; t < 2; t++) {
        #pragma unroll
        for (int h = 0; h < 2; h++) {
            int q = q0 + wm * 32 + t * 16 + h * 8 + g;
            float off = g_off[q];
            uint8_t* dst = g_ws8 + (size_t)q * C_ + c0 + wn * 64;
            float lmax = -3.4e38f;
            #pragma unroll
            for (int n = 0; n < 8; n++) {
                __half2 hv = *(__half2*)&acc[t][n][h];
                float v0 = __low2float(hv) * inv_t;
                float v1 = __high2float(hv) * inv_t;
                lmax = fmaxf(lmax, fmaxf(v0, v1));
                int u0 = __float2int_rn(fminf(fmaxf((v0 - off) * QS, 0.f), 255.f));
                int u1 = __float2int_rn(fminf(fmaxf((v1 - off) * QS, 0.f), 255.f));
                *(unsigned short*)(dst + n * 8 + tig * 2) =
                    (unsigned short)(u0 | (u1 << 8));
            }
            lmax = fmaxf(lmax, __shfl_xor_sync(0xffffffffu, lmax, 1));
            lmax = fmaxf(lmax, __shfl_xor_sync(0xffffffffu, lmax, 2));
            if (tig == 0) {
                int ut = __float2int_rn(fminf(fmaxf((lmax - off) * QS, 0.f), 255.f));
                g_tmax8[(size_t)q * NT64 + nt * 2 + wn] = (uint8_t)ut;
                atomicMax(&g_rowmax[q], fenc(lmax));
            }
        }
    }
}

// ---------------- kernel 3a: select + exact rescore + softmax -> weight lists --
__global__ void __launch_bounds__(256) sel_kernel(
    const float* __restrict__ x, const float* __restrict__ keys,
    const float* __restrict__ logt)
{
    __shared__ float xs[D_];
    __shared__ int   tlist[NT64];
    __shared__ int   craw[CAP];
    __shared__ int   cidx[CAP];
    __shared__ float cw[CAP];
    __shared__ float red[256];
    __shared__ int   tcnt, cnt;

    int q = blockIdx.x;
    int tid = threadIdx.x;
    float inv_t = __expf(-logt[0]);

    xs[tid] = x[(size_t)q * D_ + tid];
    xs[tid + 256] = x[(size_t)q * D_ + tid + 256];
    if (tid == 0) { tcnt = 0; cnt = 0; }
    __syncthreads();

    float mx = fdec(g_rowmax[q]);
    float thr = mx - (MARGIN + 0.001f * fabsf(mx) + 0.8f * inv_t);
    float off = g_off[q];
    int thr_u = (int)floorf((thr - off) * QS);
    thr_u = min(max(thr_u, 0), 254);
    uint32_t thrb = (uint32_t)thr_u * 0x01010101u;

    // phase 1: tile-max scan (1 KB)
    uint32_t tw = ((const uint32_t*)(g_tmax8 + (size_t)q * NT64))[tid];
    uint32_t tmsk = __vcmpgtu4(tw, thrb);
    while (tmsk) {
        int b = (__ffs(tmsk) - 1) >> 3;
        tmsk &= ~(0xFFu << (b * 8));
        int p = atomicAdd(&tcnt, 1);
        tlist[p] = tid * 4 + b;
    }
    __syncthreads();
    int ntl = min(tcnt, NT64);

    // phase 2: candidate extraction, half-warp per tile
    int hw = tid >> 4, l16 = tid & 15;
    const uint8_t* wrow = g_ws8 + (size_t)q * C_;
    for (int t = hw; t < ntl; t += 16) {
        int tile = tlist[t];
        uint32_t v = __ldg((const uint32_t*)(wrow + tile * 64) + l16);
        uint32_t m = __vcmpgtu4(v, thrb);
        while (m) {
            int b = (__ffs(m) - 1) >> 3;
            m &= ~(0xFFu << (b * 8));
            int p = atomicAdd(&cnt, 1);
            if (p < CAP) craw[p] = tile * 64 + l16 * 4 + b;
        }
    }
    __syncthreads();
    int n = min(cnt, CAP);

    // parallel rank sort (indices distinct); deterministic order
    for (int i = tid; i < n; i += 256) {
        int key = craw[i];
        int rank = 0;
        for (int j = 0; j < n; j++) rank += (craw[j] < key);
        cidx[rank] = key;
    }
    __syncthreads();

    // exact fp32 ws for selected candidates (one warp per candidate, 8 warps)
    int w = tid >> 5, lane = tid & 31;
    for (int i = w; i < n; i += 8) {
        const float* kr = keys + (size_t)cidx[i] * D_;
        float s = 0.f;
        #pragma unroll
        for (int kk = 0; kk < 16; kk++) s += xs[lane + kk * 32] * __ldg(kr + lane + kk * 32);
        #pragma unroll
        for (int o = 16; o; o >>= 1) s += __shfl_xor_sync(0xffffffffu, s, o);
        if (lane == 0) cw[i] = s * inv_t;
    }
    __syncthreads();

    // exact max over selected
    float lm = -3.4e38f;
    for (int i = tid; i < n; i += 256) lm = fmaxf(lm, cw[i]);
    red[tid] = lm; __syncthreads();
    for (int s2 = 128; s2; s2 >>= 1) { if (tid < s2) red[tid] = fmaxf(red[tid], red[tid + s2]); __syncthreads(); }
    float m = red[0]; __syncthreads();

    // exp + sum
    float ls = 0.f;
    for (int i = tid; i < n; i += 256) { float e = __expf(cw[i] - m); cw[i] = e; ls += e; }
    red[tid] = ls; __syncthreads();
    for (int s2 = 128; s2; s2 >>= 1) { if (tid < s2) red[tid] += red[tid + s2]; __syncthreads(); }
    float invS = 1.0f / red[0]; __syncthreads();

    // write compact normalized weight list
    for (int i = tid; i < n; i += 256) {
        g_widx[(size_t)q * CAP + i] = cidx[i];
        g_w[(size_t)q * CAP + i] = cw[i] * invS;
    }
    if (tid == 0) g_n[q] = n;
}

// ---------------- kernel 3b: weighted gather (2 blocks per row) ----------------
__global__ void __launch_bounds__(256) gather_kernel(
    const float* __restrict__ values, float* __restrict__ out)
{
    __shared__ int   sidx[CAP];
    __shared__ float sw[CAP];

    int q = blockIdx.x >> 1;
    int half = blockIdx.x & 1;
    int tid = threadIdx.x;
    int n = g_n[q];

    for (int i = tid; i < n; i += 256) {
        sidx[i] = g_widx[(size_t)q * CAP + i];
        sw[i]   = g_w[(size_t)q * CAP + i];
    }
    __syncthreads();

    int d = half * 256 + tid;
    float a0 = 0.f;
    #pragma unroll 8
    for (int i = 0; i < n; i++) {
        a0 += sw[i] * __ldg(values + (size_t)sidx[i] * D_ + d);
    }
    out[(size_t)q * D_ + d] = a0;
}

// ---------------- launch ----------------
extern "C" void kernel_launch(void* const* d_in, const int* in_sizes, int n_in,
                              void* d_out, int out_size) {
    const float* x      = (const float*)d_in[0];
    const float* keys   = (const float*)d_in[1];
    const float* values = (const float*)d_in[2];
    const float* logt   = (const float*)d_in[3];
    float* out = (float*)d_out;

    static bool attr_done = false;
    if (!attr_done) {
        cudaFuncSetAttribute(gemm_kernel, cudaFuncAttributeMaxDynamicSharedMemorySize, SMEM_ALLOC);
        attr_done = true;
    }

    conv_kernel<<<CONV_STRIDE / 256, 256>>>(keys);
    xnorm_kernel<<<B_ / 8, 256>>>(x, logt);
    gemm_kernel<<<(B_ / 128) * (C_ / 128), 256, SMEM_ALLOC>>>(logt);
    sel_kernel<<<B_, 256>>>(x, keys, logt);
    gather_kernel<<<B_ * 2, 256>>>(values, out);
}